// round 1
// baseline (speedup 1.0000x reference)
#include <cuda_runtime.h>
#include <math.h>

#define Bb 16
#define Hh 512
#define Ww 512
#define HW (Hh*Ww)
#define BHW (Bb*Hh*Ww)
#define Lsteps 10

// ---- scratch in device globals (no allocation allowed) ----
__device__ float  d_res[10 * BHW];      // residuals[1..10]
__device__ float2 d_phiA[10 * BHW];     // phi ping buffer
__device__ float2 d_phiB[10 * BHW];     // phi pong buffer
__device__ float  d_img[BHW];           // current image
__device__ float  d_a[2 * BHW];         // -res * grad(image)
__device__ float  d_t[2 * BHW];         // blur temp (after horizontal pass)
__device__ float  d_v[2 * BHW];         // velocity field

// 7-tap gaussian, sigma=2 (normalized, matches jnp float32 to <1ulp)
__device__ __constant__ float GW[7] = {
    0.070159329f, 0.131074882f, 0.190712821f, 0.216105908f,
    0.190712821f, 0.131074882f, 0.070159329f
};

__device__ __forceinline__ float bilerp1(const float* __restrict__ p, float px, float py) {
    float x0f = floorf(px), y0f = floorf(py);
    float wx = px - x0f, wy = py - y0f;
    int x0 = (int)x0f, y0 = (int)y0f;
    int x1 = x0 + 1, y1 = y0 + 1;
    bool bx0 = (x0 >= 0) && (x0 < Ww), bx1 = (x1 >= 0) && (x1 < Ww);
    bool by0 = (y0 >= 0) && (y0 < Hh), by1 = (y1 >= 0) && (y1 < Hh);
    float Ia = (bx0 && by0) ? p[y0 * Ww + x0] : 0.f;
    float Ib = (bx1 && by0) ? p[y0 * Ww + x1] : 0.f;
    float Ic = (bx0 && by1) ? p[y1 * Ww + x0] : 0.f;
    float Id = (bx1 && by1) ? p[y1 * Ww + x1] : 0.f;
    return Ia * (1.f - wx) * (1.f - wy) + Ib * wx * (1.f - wy)
         + Ic * (1.f - wx) * wy        + Id * wx * wy;
}

__device__ __forceinline__ float2 bilerp2(const float2* __restrict__ p, float px, float py) {
    float x0f = floorf(px), y0f = floorf(py);
    float wx = px - x0f, wy = py - y0f;
    int x0 = (int)x0f, y0 = (int)y0f;
    int x1 = x0 + 1, y1 = y0 + 1;
    bool bx0 = (x0 >= 0) && (x0 < Ww), bx1 = (x1 >= 0) && (x1 < Ww);
    bool by0 = (y0 >= 0) && (y0 < Hh), by1 = (y1 >= 0) && (y1 < Hh);
    float2 z = make_float2(0.f, 0.f);
    float2 Ia = (bx0 && by0) ? p[y0 * Ww + x0] : z;
    float2 Ib = (bx1 && by0) ? p[y0 * Ww + x1] : z;
    float2 Ic = (bx0 && by1) ? p[y1 * Ww + x0] : z;
    float2 Id = (bx1 && by1) ? p[y1 * Ww + x1] : z;
    float w00 = (1.f - wx) * (1.f - wy), w10 = wx * (1.f - wy);
    float w01 = (1.f - wx) * wy,         w11 = wx * wy;
    float2 r;
    r.x = Ia.x * w00 + Ib.x * w10 + Ic.x * w01 + Id.x * w11;
    r.y = Ia.y * w00 + Ib.y * w10 + Ic.y * w01 + Id.y * w11;
    return r;
}

// K1: a = -res * sobel_gradient(img), replicate padding
__global__ void k_grad(const float* __restrict__ img, const float* __restrict__ res) {
    int idx = blockIdx.x * blockDim.x + threadIdx.x;
    if (idx >= BHW) return;
    int x = idx & (Ww - 1);
    int y = (idx >> 9) & (Hh - 1);
    int base = idx - (y << 9) - x;   // b*H*W
    int xm = max(x - 1, 0), xp = min(x + 1, Ww - 1);
    int ym = max(y - 1, 0), yp = min(y + 1, Hh - 1);
    const float* p = img + base;
    float Imm = p[ym * Ww + xm], Im0 = p[ym * Ww + x], Imp = p[ym * Ww + xp];
    float I0m = p[y  * Ww + xm],                        I0p = p[y  * Ww + xp];
    float Ipm = p[yp * Ww + xm], Ip0 = p[yp * Ww + x], Ipp = p[yp * Ww + xp];
    float gx = (-Imm + Imp - 2.f * I0m + 2.f * I0p - Ipm + Ipp) * 0.125f;
    float gy = (-Imm - 2.f * Im0 - Imp + Ipm + 2.f * Ip0 + Ipp) * 0.125f;
    float r = res[idx];
    d_a[idx]        = -r * gx;
    d_a[BHW + idx]  = -r * gy;
}

// K2: horizontal gaussian (zero pad), a -> t (both channels)
__global__ void k_blurH() {
    int idx = blockIdx.x * blockDim.x + threadIdx.x;
    if (idx >= BHW) return;
    int x = idx & (Ww - 1);
    int rowstart = idx - x;
    #pragma unroll
    for (int c = 0; c < 2; c++) {
        const float* p = d_a + c * BHW + rowstart;
        float s = 0.f;
        #pragma unroll
        for (int k = 0; k < 7; k++) {
            int xx = x + k - 3;
            if (xx >= 0 && xx < Ww) s += GW[k] * p[xx];
        }
        d_t[c * BHW + idx] = s;
    }
}

// K3: vertical gaussian (zero pad), t -> v
__global__ void k_blurV() {
    int idx = blockIdx.x * blockDim.x + threadIdx.x;
    if (idx >= BHW) return;
    int x = idx & (Ww - 1);
    int y = (idx >> 9) & (Hh - 1);
    int base = idx - (y << 9) - x;
    #pragma unroll
    for (int c = 0; c < 2; c++) {
        const float* p = d_t + c * BHW + base;
        float s = 0.f;
        #pragma unroll
        for (int k = 0; k < 7; k++) {
            int yy = y + k - 3;
            if (yy >= 0 && yy < Hh) s += GW[k] * p[yy * Ww + x];
        }
        d_v[c * BHW + idx] = s;
    }
}

// K4: res_next = res - div(res*v)/L   (3x3 correlation, zero pad)
__global__ void k_div(const float* __restrict__ res, float* __restrict__ res_next) {
    int idx = blockIdx.x * blockDim.x + threadIdx.x;
    if (idx >= BHW) return;
    int x = idx & (Ww - 1);
    int y = (idx >> 9) & (Hh - 1);
    int base = idx - (y << 9) - x;
    const float* rp = res + base;
    const float* v0 = d_v + base;
    const float* v1 = d_v + BHW + base;

    auto w0 = [&](int yy, int xx) -> float {
        if (xx < 0 || xx >= Ww || yy < 0 || yy >= Hh) return 0.f;
        int o = yy * Ww + xx;
        return rp[o] * v0[o];
    };
    auto w1 = [&](int yy, int xx) -> float {
        if (xx < 0 || xx >= Ww || yy < 0 || yy >= Hh) return 0.f;
        int o = yy * Ww + xx;
        return rp[o] * v1[o];
    };

    float f =
        (-w0(y - 1, x - 1) + w0(y - 1, x + 1)
         - 2.f * w0(y, x - 1) + 2.f * w0(y, x + 1)
         - w0(y + 1, x - 1) + w0(y + 1, x + 1)
         - w1(y - 1, x - 1) - 2.f * w1(y - 1, x) - w1(y - 1, x + 1)
         + w1(y + 1, x - 1) + 2.f * w1(y + 1, x) + w1(y + 1, x + 1))
        * (0.125f / (float)Lsteps);

    res_next[idx] = res[idx] - f;
}

// K5: warp all existing phis through new deformation D = id - v/L; append D
__global__ void k_warp(int i, const float2* __restrict__ src, float2* __restrict__ dst) {
    int idx = blockIdx.x * blockDim.x + threadIdx.x;
    if (idx >= BHW) return;
    int x = idx & (Ww - 1);
    int y = (idx >> 9) & (Hh - 1);
    int base = idx - (y << 9) - x;
    const float invL = 1.f / (float)Lsteps;
    float px = (float)x - d_v[idx] * invL;
    float py = (float)y - d_v[BHW + idx] * invL;

    for (int j = 0; j < i; j++) {
        dst[j * BHW + idx] = bilerp2(src + j * BHW + base, px, py);
    }
    dst[i * BHW + idx] = make_float2(px, py);
}

// K6+K7 fused: residuals_sum, mask, image update
__global__ void k_final(int i, const float2* __restrict__ phi,
                        const float* __restrict__ resbase,
                        const float* __restrict__ src, const float* __restrict__ seg,
                        float* __restrict__ out) {
    int idx = blockIdx.x * blockDim.x + threadIdx.x;
    if (idx >= BHW) return;
    int x = idx & (Ww - 1);
    int y = (idx >> 9) & (Hh - 1);
    int base = idx - (y << 9) - x;

    // residuals[i+1] lives in slot i
    float acc = resbase[i * BHW + idx];
    for (int j = 1; j <= i; j++) {
        float2 p = phi[j * BHW + idx];
        acc += bilerp1(resbase + (j - 1) * BHW + base, p.x, p.y);
    }
    float2 p0 = phi[idx];
    float s = bilerp1(src + base, p0.x, p0.y);
    float m = bilerp1(seg + base, p0.x, p0.y);
    const float scale = (0.05f * 0.05f) / (float)Lsteps;  // MU^2 / L
    out[idx] = s + acc * scale * m;
}

extern "C" void kernel_launch(void* const* d_in, const int* in_sizes, int n_in,
                              void* d_out, int out_size) {
    const float* src = (const float*)d_in[0];
    const float* z0  = (const float*)d_in[1];
    const float* seg = (const float*)d_in[2];

    float*  res;  cudaGetSymbolAddress((void**)&res,  d_res);
    float2* pA;   cudaGetSymbolAddress((void**)&pA,   d_phiA);
    float2* pB;   cudaGetSymbolAddress((void**)&pB,   d_phiB);
    float*  img;  cudaGetSymbolAddress((void**)&img,  d_img);

    const int threads = 256;
    const int blocks = BHW / threads;

    for (int i = 0; i < Lsteps; i++) {
        const float* img_in = (i == 0) ? src : img;
        const float* res_i  = (i == 0) ? z0  : res + (size_t)(i - 1) * BHW;

        k_grad<<<blocks, threads>>>(img_in, res_i);
        k_blurH<<<blocks, threads>>>();
        k_blurV<<<blocks, threads>>>();
        k_div<<<blocks, threads>>>(res_i, res + (size_t)i * BHW);

        float2* dst = (i & 1) ? pB : pA;
        const float2* s2 = (i & 1) ? pA : pB;
        k_warp<<<blocks, threads>>>(i, s2, dst);

        float* outp = (i == Lsteps - 1) ? (float*)d_out : img;
        k_final<<<blocks, threads>>>(i, dst, res, src, seg, outp);
    }
}

// round 2
// speedup vs baseline: 1.0760x; 1.0760x over previous
#include <cuda_runtime.h>
#include <math.h>

#define Bb 16
#define Hh 512
#define Ww 512
#define HW (Hh*Ww)
#define BHW (Bb*HW)
#define Lsteps 10

// ---- scratch in device globals (no allocation allowed) ----
__device__ float  d_res[10 * BHW];      // residuals[1..10]
__device__ float2 d_phiA[10 * BHW];     // phi ping buffer
__device__ float2 d_phiB[10 * BHW];     // phi pong buffer
__device__ float  d_img[BHW];           // current image
__device__ float  d_v[2 * BHW];         // velocity field

// 7-tap gaussian, sigma=2 (normalized)
__device__ __constant__ float GW[7] = {
    0.070159329f, 0.131074882f, 0.190712821f, 0.216105908f,
    0.190712821f, 0.131074882f, 0.070159329f
};

// ---------- tiled fused velocity kernel geometry ----------
#define TX 32
#define TY 32
#define IMW 42   // img tile: halo ±5
#define IMH 42
#define RW  40   // res / a tile: halo ±4
#define RH  40
#define TW  34   // t (blurH) tile: x halo ±1, y halo ±4
#define TH  40
#define VW  34   // v tile: halo ±1
#define VH  34

// Fused: grad(img) -> a = -res*grad -> blurH -> blurV = v -> div(res*v) -> res_next
// Also writes v to global (needed by warp kernel).
__global__ __launch_bounds__(256) void k_vel(const float* __restrict__ img,
                                             const float* __restrict__ res,
                                             float* __restrict__ res_next) {
    __shared__ float s_img[IMH * IMW];
    __shared__ float s_res[RH * RW];
    __shared__ float s_a0[RH * RW];
    __shared__ float s_a1[RH * RW];
    __shared__ float s_t0[TH * TW];
    __shared__ float s_t1[TH * TW];
    __shared__ float s_v0[VH * VW];
    __shared__ float s_v1[VH * VW];

    const int b  = blockIdx.z;
    const int X0 = blockIdx.x * TX;
    const int Y0 = blockIdx.y * TY;
    const float* ip = img + (size_t)b * HW;
    const float* rp = res + (size_t)b * HW;
    const int t = threadIdx.x;

    // load img tile with replicate clamp (halo ±5)
    for (int k = t; k < IMH * IMW; k += 256) {
        int ly = k / IMW, lx = k % IMW;
        int gy = min(max(Y0 - 5 + ly, 0), Hh - 1);
        int gx = min(max(X0 - 5 + lx, 0), Ww - 1);
        s_img[k] = ip[gy * Ww + gx];
    }
    // load res tile zero-padded (halo ±4)
    for (int k = t; k < RH * RW; k += 256) {
        int ly = k / RW, lx = k % RW;
        int gy = Y0 - 4 + ly, gx = X0 - 4 + lx;
        s_res[k] = (gy >= 0 && gy < Hh && gx >= 0 && gx < Ww) ? rp[gy * Ww + gx] : 0.f;
    }
    __syncthreads();

    // a = -res * sobel(img); zero outside image (zero-pad semantics for blur)
    for (int k = t; k < RH * RW; k += 256) {
        int ly = k / RW, lx = k % RW;
        int gy = Y0 - 4 + ly, gx = X0 - 4 + lx;
        float a0 = 0.f, a1 = 0.f;
        if (gy >= 0 && gy < Hh && gx >= 0 && gx < Ww) {
            const float* c = &s_img[(ly + 1) * IMW + (lx + 1)];
            float Imm = c[-IMW - 1], Im0 = c[-IMW], Imp = c[-IMW + 1];
            float I0m = c[-1],                        I0p = c[1];
            float Ipm = c[IMW - 1],  Ip0 = c[IMW],  Ipp = c[IMW + 1];
            float gxv = (-Imm + Imp - 2.f * I0m + 2.f * I0p - Ipm + Ipp) * 0.125f;
            float gyv = (-Imm - 2.f * Im0 - Imp + Ipm + 2.f * Ip0 + Ipp) * 0.125f;
            float r = s_res[k];
            a0 = -r * gxv;
            a1 = -r * gyv;
        }
        s_a0[k] = a0;
        s_a1[k] = a1;
    }
    __syncthreads();

    // horizontal blur: t[ly][lx] covers x in [-1, 32], y in [-4, 35]
    for (int k = t; k < TH * TW; k += 256) {
        int ly = k / TW, lx = k % TW;
        float s0 = 0.f, s1 = 0.f;
        const float* a0p = &s_a0[ly * RW + lx];
        const float* a1p = &s_a1[ly * RW + lx];
        #pragma unroll
        for (int kk = 0; kk < 7; kk++) {
            s0 += GW[kk] * a0p[kk];
            s1 += GW[kk] * a1p[kk];
        }
        s_t0[k] = s0;
        s_t1[k] = s1;
    }
    __syncthreads();

    // vertical blur: v[ly][lx] covers x,y in [-1, 32]
    for (int k = t; k < VH * VW; k += 256) {
        int ly = k / VW, lx = k % VW;
        float s0 = 0.f, s1 = 0.f;
        const float* t0p = &s_t0[ly * TW + lx];
        const float* t1p = &s_t1[ly * TW + lx];
        #pragma unroll
        for (int kk = 0; kk < 7; kk++) {
            s0 += GW[kk] * t0p[kk * TW];
            s1 += GW[kk] * t1p[kk * TW];
        }
        s_v0[k] = s0;
        s_v1[k] = s1;
    }
    __syncthreads();

    // outputs: v and res_next = res - div(res*v)/L
    // (zero padding of div is automatic: s_res == 0 outside image)
    for (int k = t; k < TX * TY; k += 256) {
        int ty = k / TX, tx = k % TX;
        int gy = Y0 + ty, gx = X0 + tx;
        int vi = (ty + 1) * VW + (tx + 1);
        int ri = (ty + 4) * RW + (tx + 4);
        float f =
            (- s_res[ri - RW - 1] * s_v0[vi - VW - 1] + s_res[ri - RW + 1] * s_v0[vi - VW + 1]
             - 2.f * s_res[ri - 1] * s_v0[vi - 1]     + 2.f * s_res[ri + 1] * s_v0[vi + 1]
             - s_res[ri + RW - 1] * s_v0[vi + VW - 1] + s_res[ri + RW + 1] * s_v0[vi + VW + 1]
             - s_res[ri - RW - 1] * s_v1[vi - VW - 1] - 2.f * s_res[ri - RW] * s_v1[vi - VW]
             - s_res[ri - RW + 1] * s_v1[vi - VW + 1]
             + s_res[ri + RW - 1] * s_v1[vi + VW - 1] + 2.f * s_res[ri + RW] * s_v1[vi + VW]
             + s_res[ri + RW + 1] * s_v1[vi + VW + 1])
            * (0.125f / (float)Lsteps);
        int gidx = b * HW + gy * Ww + gx;
        res_next[gidx] = s_res[ri] - f;
        d_v[gidx]        = s_v0[vi];
        d_v[BHW + gidx]  = s_v1[vi];
    }
}

// ---------- bilinear helpers ----------
__device__ __forceinline__ float bilerp1(const float* __restrict__ p, float px, float py) {
    float x0f = floorf(px), y0f = floorf(py);
    float wx = px - x0f, wy = py - y0f;
    int x0 = (int)x0f, y0 = (int)y0f;
    int x1 = x0 + 1, y1 = y0 + 1;
    bool bx0 = (x0 >= 0) && (x0 < Ww), bx1 = (x1 >= 0) && (x1 < Ww);
    bool by0 = (y0 >= 0) && (y0 < Hh), by1 = (y1 >= 0) && (y1 < Hh);
    float Ia = (bx0 && by0) ? p[y0 * Ww + x0] : 0.f;
    float Ib = (bx1 && by0) ? p[y0 * Ww + x1] : 0.f;
    float Ic = (bx0 && by1) ? p[y1 * Ww + x0] : 0.f;
    float Id = (bx1 && by1) ? p[y1 * Ww + x1] : 0.f;
    return Ia * (1.f - wx) * (1.f - wy) + Ib * wx * (1.f - wy)
         + Ic * (1.f - wx) * wy        + Id * wx * wy;
}

__device__ __forceinline__ float2 bilerp2(const float2* __restrict__ p, float px, float py) {
    float x0f = floorf(px), y0f = floorf(py);
    float wx = px - x0f, wy = py - y0f;
    int x0 = (int)x0f, y0 = (int)y0f;
    int x1 = x0 + 1, y1 = y0 + 1;
    bool bx0 = (x0 >= 0) && (x0 < Ww), bx1 = (x1 >= 0) && (x1 < Ww);
    bool by0 = (y0 >= 0) && (y0 < Hh), by1 = (y1 >= 0) && (y1 < Hh);
    float2 z = make_float2(0.f, 0.f);
    float2 Ia = (bx0 && by0) ? p[y0 * Ww + x0] : z;
    float2 Ib = (bx1 && by0) ? p[y0 * Ww + x1] : z;
    float2 Ic = (bx0 && by1) ? p[y1 * Ww + x0] : z;
    float2 Id = (bx1 && by1) ? p[y1 * Ww + x1] : z;
    float w00 = (1.f - wx) * (1.f - wy), w10 = wx * (1.f - wy);
    float w01 = (1.f - wx) * wy,         w11 = wx * wy;
    float2 r;
    r.x = Ia.x * w00 + Ib.x * w10 + Ic.x * w01 + Id.x * w11;
    r.y = Ia.y * w00 + Ib.y * w10 + Ic.y * w01 + Id.y * w11;
    return r;
}

// Fused: warp all phis through D = id - v/L (append D), residual sum using the
// freshly-warped phis, mask + image update.
__global__ void k_warpfinal(int i, const float2* __restrict__ srcphi,
                            float2* __restrict__ dst,
                            const float* __restrict__ resb,
                            const float* __restrict__ srcimg,
                            const float* __restrict__ seg,
                            float* __restrict__ out) {
    int idx = blockIdx.x * blockDim.x + threadIdx.x;
    if (idx >= BHW) return;
    int x = idx & (Ww - 1);
    int y = (idx >> 9) & (Hh - 1);
    int base = idx - (y << 9) - x;

    const float invL = 1.f / (float)Lsteps;
    float px = (float)x - d_v[idx] * invL;
    float py = (float)y - d_v[BHW + idx] * invL;

    // residuals[i+1] lives in slot i
    float acc = resb[(size_t)i * BHW + idx];
    float2 p0 = make_float2(px, py);

    for (int j = 0; j < i; j++) {
        float2 p = bilerp2(srcphi + (size_t)j * BHW + base, px, py);
        dst[(size_t)j * BHW + idx] = p;
        if (j == 0) p0 = p;
        else acc += bilerp1(resb + (size_t)(j - 1) * BHW + base, p.x, p.y);
    }
    dst[(size_t)i * BHW + idx] = make_float2(px, py);
    if (i >= 1) acc += bilerp1(resb + (size_t)(i - 1) * BHW + base, px, py);

    float s = bilerp1(srcimg + base, p0.x, p0.y);
    float m = bilerp1(seg + base, p0.x, p0.y);
    const float scale = 2.5e-4f;  // MU^2 / L
    out[idx] = s + acc * scale * m;
}

extern "C" void kernel_launch(void* const* d_in, const int* in_sizes, int n_in,
                              void* d_out, int out_size) {
    const float* src = (const float*)d_in[0];
    const float* z0  = (const float*)d_in[1];
    const float* seg = (const float*)d_in[2];

    float*  res;  cudaGetSymbolAddress((void**)&res,  d_res);
    float2* pA;   cudaGetSymbolAddress((void**)&pA,   d_phiA);
    float2* pB;   cudaGetSymbolAddress((void**)&pB,   d_phiB);
    float*  img;  cudaGetSymbolAddress((void**)&img,  d_img);

    const int threads = 256;
    const int blocks = BHW / threads;
    dim3 vgrid(Ww / TX, Hh / TY, Bb);

    for (int i = 0; i < Lsteps; i++) {
        const float* img_in = (i == 0) ? src : img;
        const float* res_i  = (i == 0) ? z0  : res + (size_t)(i - 1) * BHW;

        k_vel<<<vgrid, 256>>>(img_in, res_i, res + (size_t)i * BHW);

        float2* dst = (i & 1) ? pB : pA;
        const float2* s2 = (i & 1) ? pA : pB;
        float* outp = (i == Lsteps - 1) ? (float*)d_out : img;
        k_warpfinal<<<blocks, threads>>>(i, s2, dst, res, src, seg, outp);
    }
}

// round 5
// speedup vs baseline: 1.2194x; 1.1333x over previous
#include <cuda_runtime.h>
#include <cuda_fp16.h>
#include <math.h>

#define Bb 16
#define Hh 512
#define Ww 512
#define HW (Hh*Ww)
#define BHW (Bb*HW)
#define Lsteps 10

// ---- scratch in device globals (no allocation allowed) ----
__device__ float   d_res[10 * BHW];     // residuals[1..10] fp32 master (slot k = residuals[k+1])
__device__ __half  d_res16[10 * BHW];   // fp16 shadow for gathers
__device__ __half2 d_uA[10 * BHW];      // phi displacement ping (u = phi - id)
__device__ __half2 d_uB[10 * BHW];      // phi displacement pong
__device__ float   d_img[BHW];          // current image

// 7-tap gaussian, sigma=2 (normalized)
__device__ __constant__ float GW[7] = {
    0.070159329f, 0.131074882f, 0.190712821f, 0.216105908f,
    0.190712821f, 0.131074882f, 0.070159329f
};

// ---------- tiled fused velocity kernel geometry ----------
#define TX 32
#define TY 32
#define IMW 42   // img tile: halo ±5
#define IMH 42
#define RW  40   // res / a tile: halo ±4
#define RH  40
#define TW  34   // t (blurH) tile: x halo ±1, y halo ±4
#define TH  40
#define VW  34   // v tile: halo ±1
#define VH  34
#define POOL 7520   // floats; aliased buffer pool (30KB)

// Fused: grad(img) -> a=-res*grad -> blurH -> blurV=v -> div(res*v) -> res_next
// Writes res_next (fp32 + fp16 shadow) and u_i = -v/L (half2) into BOTH phi buffers.
__global__ __launch_bounds__(256) void k_vel(const float* __restrict__ img,
                                             const float* __restrict__ res,
                                             float* __restrict__ res_next,
                                             __half* __restrict__ res16out,
                                             __half2* __restrict__ uA,
                                             __half2* __restrict__ uB) {
    __shared__ float pool[POOL];
    float* s_res = pool;            // 1600, persistent
    float* s_a0  = pool + 1600;     // 1600
    float* s_a1  = pool + 3200;     // 1600
    float* s_img = pool + 4800;     // 1764, dies after 'a' phase
    float* s_t0  = pool + 4800;     // 1360, overlays img
    float* s_t1  = pool + 6160;     // 1360
    float* s_v0  = pool + 1600;     // 1156, overlays a0/a1 (dead after blurH)
    float* s_v1  = pool + 2756;     // 1156

    const int b  = blockIdx.z;
    const int X0 = blockIdx.x * TX;
    const int Y0 = blockIdx.y * TY;
    const float* ip = img + (size_t)b * HW;
    const float* rp = res + (size_t)b * HW;
    const int t = threadIdx.x;

    for (int k = t; k < IMH * IMW; k += 256) {
        int ly = k / IMW, lx = k % IMW;
        int gy = min(max(Y0 - 5 + ly, 0), Hh - 1);
        int gx = min(max(X0 - 5 + lx, 0), Ww - 1);
        s_img[k] = ip[gy * Ww + gx];
    }
    for (int k = t; k < RH * RW; k += 256) {
        int ly = k / RW, lx = k % RW;
        int gy = Y0 - 4 + ly, gx = X0 - 4 + lx;
        s_res[k] = (gy >= 0 && gy < Hh && gx >= 0 && gx < Ww) ? rp[gy * Ww + gx] : 0.f;
    }
    __syncthreads();

    // a = -res * sobel(img); zero outside image
    for (int k = t; k < RH * RW; k += 256) {
        int ly = k / RW, lx = k % RW;
        int gy = Y0 - 4 + ly, gx = X0 - 4 + lx;
        float a0 = 0.f, a1 = 0.f;
        if (gy >= 0 && gy < Hh && gx >= 0 && gx < Ww) {
            const float* c = &s_img[(ly + 1) * IMW + (lx + 1)];
            float Imm = c[-IMW - 1], Im0 = c[-IMW], Imp = c[-IMW + 1];
            float I0m = c[-1],                        I0p = c[1];
            float Ipm = c[IMW - 1],  Ip0 = c[IMW],  Ipp = c[IMW + 1];
            float gxv = (-Imm + Imp - 2.f * I0m + 2.f * I0p - Ipm + Ipp) * 0.125f;
            float gyv = (-Imm - 2.f * Im0 - Imp + Ipm + 2.f * Ip0 + Ipp) * 0.125f;
            float r = s_res[k];
            a0 = -r * gxv;
            a1 = -r * gyv;
        }
        s_a0[k] = a0;
        s_a1[k] = a1;
    }
    __syncthreads();

    // horizontal blur (writes t over dead img region)
    for (int k = t; k < TH * TW; k += 256) {
        int ly = k / TW, lx = k % TW;
        float s0 = 0.f, s1 = 0.f;
        const float* a0p = &s_a0[ly * RW + lx];
        const float* a1p = &s_a1[ly * RW + lx];
        #pragma unroll
        for (int kk = 0; kk < 7; kk++) {
            s0 += GW[kk] * a0p[kk];
            s1 += GW[kk] * a1p[kk];
        }
        s_t0[k] = s0;
        s_t1[k] = s1;
    }
    __syncthreads();

    // vertical blur (writes v over dead a region)
    for (int k = t; k < VH * VW; k += 256) {
        int ly = k / VW, lx = k % VW;
        float s0 = 0.f, s1 = 0.f;
        const float* t0p = &s_t0[ly * TW + lx];
        const float* t1p = &s_t1[ly * TW + lx];
        #pragma unroll
        for (int kk = 0; kk < 7; kk++) {
            s0 += GW[kk] * t0p[kk * TW];
            s1 += GW[kk] * t1p[kk * TW];
        }
        s_v0[k] = s0;
        s_v1[k] = s1;
    }
    __syncthreads();

    const float invL = 1.f / (float)Lsteps;
    for (int k = t; k < TX * TY; k += 256) {
        int ty = k / TX, tx = k % TX;
        int gy = Y0 + ty, gx = X0 + tx;
        int vi = (ty + 1) * VW + (tx + 1);
        int ri = (ty + 4) * RW + (tx + 4);
        float f =
            (- s_res[ri - RW - 1] * s_v0[vi - VW - 1] + s_res[ri - RW + 1] * s_v0[vi - VW + 1]
             - 2.f * s_res[ri - 1] * s_v0[vi - 1]     + 2.f * s_res[ri + 1] * s_v0[vi + 1]
             - s_res[ri + RW - 1] * s_v0[vi + VW - 1] + s_res[ri + RW + 1] * s_v0[vi + VW + 1]
             - s_res[ri - RW - 1] * s_v1[vi - VW - 1] - 2.f * s_res[ri - RW] * s_v1[vi - VW]
             - s_res[ri - RW + 1] * s_v1[vi - VW + 1]
             + s_res[ri + RW - 1] * s_v1[vi + VW - 1] + 2.f * s_res[ri + RW] * s_v1[vi + VW]
             + s_res[ri + RW + 1] * s_v1[vi + VW + 1])
            * (0.125f / (float)Lsteps);
        int gidx = b * HW + gy * Ww + gx;
        float rv = s_res[ri] - f;
        res_next[gidx] = rv;
        res16out[gidx] = __float2half(rv);
        __half2 uh = __floats2half2_rn(-s_v0[vi] * invL, -s_v1[vi] * invL);
        uA[gidx] = uh;
        uB[gidx] = uh;
    }
}

// ---------- gather helpers ----------
// Absolute-coordinate gather of a displacement-encoded phi field (zero-pad on
// the ABSOLUTE field, matching grid_sample semantics).
__device__ __forceinline__ float2 gather_phi(const __half2* __restrict__ u, float px, float py) {
    float x0f = floorf(px), y0f = floorf(py);
    float wx = px - x0f, wy = py - y0f;
    int x0 = (int)x0f, y0 = (int)y0f;
    float w00 = (1.f - wx) * (1.f - wy), w10 = wx * (1.f - wy);
    float w01 = (1.f - wx) * wy,         w11 = wx * wy;
    if (x0 >= 0 && y0 >= 0 && x0 < Ww - 1 && y0 < Hh - 1) {
        const __half2* r0 = u + y0 * Ww + x0;
        float2 a = __half22float2(r0[0]);
        float2 bb = __half22float2(r0[1]);
        float2 c = __half22float2(r0[Ww]);
        float2 d = __half22float2(r0[Ww + 1]);
        float ux = a.x * w00 + bb.x * w10 + c.x * w01 + d.x * w11;
        float uy = a.y * w00 + bb.y * w10 + c.y * w01 + d.y * w11;
        return make_float2(px + ux, py + uy);
    }
    int x1 = x0 + 1, y1 = y0 + 1;
    float rx = 0.f, ry = 0.f;
    #define PHITAP(xt, yt, w) \
        if ((xt) >= 0 && (xt) < Ww && (yt) >= 0 && (yt) < Hh) { \
            float2 uu = __half22float2(u[(yt) * Ww + (xt)]); \
            rx += (w) * ((float)(xt) + uu.x); \
            ry += (w) * ((float)(yt) + uu.y); \
        }
    PHITAP(x0, y0, w00) PHITAP(x1, y0, w10) PHITAP(x0, y1, w01) PHITAP(x1, y1, w11)
    #undef PHITAP
    return make_float2(rx, ry);
}

__device__ __forceinline__ float gather_res16(const __half* __restrict__ p, float px, float py) {
    float x0f = floorf(px), y0f = floorf(py);
    float wx = px - x0f, wy = py - y0f;
    int x0 = (int)x0f, y0 = (int)y0f;
    float Ia, Ib, Ic, Id;
    if (x0 >= 0 && y0 >= 0 && x0 < Ww - 1 && y0 < Hh - 1) {
        const __half* r0 = p + y0 * Ww + x0;
        Ia = __half2float(r0[0]); Ib = __half2float(r0[1]);
        Ic = __half2float(r0[Ww]); Id = __half2float(r0[Ww + 1]);
    } else {
        int x1 = x0 + 1, y1 = y0 + 1;
        bool bx0 = (x0 >= 0) && (x0 < Ww), bx1 = (x1 >= 0) && (x1 < Ww);
        bool by0 = (y0 >= 0) && (y0 < Hh), by1 = (y1 >= 0) && (y1 < Hh);
        Ia = (bx0 && by0) ? __half2float(p[y0 * Ww + x0]) : 0.f;
        Ib = (bx1 && by0) ? __half2float(p[y0 * Ww + x1]) : 0.f;
        Ic = (bx0 && by1) ? __half2float(p[y1 * Ww + x0]) : 0.f;
        Id = (bx1 && by1) ? __half2float(p[y1 * Ww + x1]) : 0.f;
    }
    return Ia * (1.f - wx) * (1.f - wy) + Ib * wx * (1.f - wy)
         + Ic * (1.f - wx) * wy        + Id * wx * wy;
}

__device__ __forceinline__ float bilerp1(const float* __restrict__ p, float px, float py) {
    float x0f = floorf(px), y0f = floorf(py);
    float wx = px - x0f, wy = py - y0f;
    int x0 = (int)x0f, y0 = (int)y0f;
    float Ia, Ib, Ic, Id;
    if (x0 >= 0 && y0 >= 0 && x0 < Ww - 1 && y0 < Hh - 1) {
        const float* r0 = p + y0 * Ww + x0;
        Ia = r0[0]; Ib = r0[1]; Ic = r0[Ww]; Id = r0[Ww + 1];
    } else {
        int x1 = x0 + 1, y1 = y0 + 1;
        bool bx0 = (x0 >= 0) && (x0 < Ww), bx1 = (x1 >= 0) && (x1 < Ww);
        bool by0 = (y0 >= 0) && (y0 < Hh), by1 = (y1 >= 0) && (y1 < Hh);
        Ia = (bx0 && by0) ? p[y0 * Ww + x0] : 0.f;
        Ib = (bx1 && by0) ? p[y0 * Ww + x1] : 0.f;
        Ic = (bx0 && by1) ? p[y1 * Ww + x0] : 0.f;
        Id = (bx1 && by1) ? p[y1 * Ww + x1] : 0.f;
    }
    return Ia * (1.f - wx) * (1.f - wy) + Ib * wx * (1.f - wy)
         + Ic * (1.f - wx) * wy        + Id * wx * wy;
}

// Fused: warp all stored phis through D_i (all sampled at the SAME point
// pd = D_i(x)), store warped displacements, gather residuals, update image.
__global__ void k_warpfinal(int i, const __half2* __restrict__ srcu,
                            __half2* __restrict__ dstu,
                            const float* __restrict__ res32,
                            const __half* __restrict__ res16,
                            const float* __restrict__ srcimg,
                            const float* __restrict__ seg,
                            float* __restrict__ out) {
    int idx = blockIdx.x * blockDim.x + threadIdx.x;
    if (idx >= BHW) return;
    int x = idx & (Ww - 1);
    int y = (idx >> 9) & (Hh - 1);
    int base = idx - (y << 9) - x;
    float fx = (float)x, fy = (float)y;

    // pd = D_i(x) = id + u_i  (slot i, written by k_vel into both buffers)
    float2 ui = __half22float2(srcu[(size_t)i * BHW + idx]);
    float2 pd = make_float2(fx + ui.x, fy + ui.y);

    // residuals_sum starts at residuals[i+1] (fp32 slot i)
    float acc = res32[(size_t)i * BHW + idx];
    float2 p0 = pd;

    for (int j = 0; j < i; j++) {
        float2 a = gather_phi(srcu + (size_t)j * BHW + base, pd.x, pd.y);
        dstu[(size_t)j * BHW + idx] = __floats2half2_rn(a.x - fx, a.y - fy);
        if (j == 0) p0 = a;
        else acc += gather_res16(res16 + (size_t)(j - 1) * BHW + base, a.x, a.y);
    }
    if (i >= 1) acc += gather_res16(res16 + (size_t)(i - 1) * BHW + base, pd.x, pd.y);

    float s = bilerp1(srcimg + base, p0.x, p0.y);
    float m = bilerp1(seg + base, p0.x, p0.y);
    const float scale = 2.5e-4f;  // MU^2 / L
    out[idx] = s + acc * scale * m;
}

extern "C" void kernel_launch(void* const* d_in, const int* in_sizes, int n_in,
                              void* d_out, int out_size) {
    const float* src = (const float*)d_in[0];
    const float* z0  = (const float*)d_in[1];
    const float* seg = (const float*)d_in[2];

    float*   res;   cudaGetSymbolAddress((void**)&res,   d_res);
    __half*  res16; cudaGetSymbolAddress((void**)&res16, d_res16);
    __half2* uA;    cudaGetSymbolAddress((void**)&uA,    d_uA);
    __half2* uB;    cudaGetSymbolAddress((void**)&uB,    d_uB);
    float*   img;   cudaGetSymbolAddress((void**)&img,   d_img);

    const int threads = 256;
    const int blocks = BHW / threads;
    dim3 vgrid(Ww / TX, Hh / TY, Bb);

    for (int i = 0; i < Lsteps; i++) {
        const float* img_in = (i == 0) ? src : img;
        const float* res_i  = (i == 0) ? z0  : res + (size_t)(i - 1) * BHW;

        k_vel<<<vgrid, 256>>>(img_in, res_i, res + (size_t)i * BHW,
                              res16 + (size_t)i * BHW,
                              uA + (size_t)i * BHW, uB + (size_t)i * BHW);

        __half2* dst = (i & 1) ? uB : uA;
        const __half2* s2 = (i & 1) ? uA : uB;
        float* outp = (i == Lsteps - 1) ? (float*)d_out : img;
        k_warpfinal<<<blocks, threads>>>(i, s2, dst, res, res16, src, seg, outp);
    }
}